// round 1
// baseline (speedup 1.0000x reference)
#include <cuda_runtime.h>

// Problem constants (fixed by reference)
#define BB   2048
#define HIST 50
#define DIM  64
#define SS   32
#define NNODE (BB*SS)   // 65536 level-1 nodes

// Scratch (allocation-free rule: __device__ globals)
__device__ float g_user[BB*DIM];          // 512 KB
__device__ float g_h1[(size_t)BB*SS*DIM]; // 16 MB  pooled level-1 vectors
__device__ float g_scores[BB];
__device__ float g_maxn;

// ---------------------------------------------------------------------------
// K1: max(n_idxs) -> g_maxn
// ---------------------------------------------------------------------------
__global__ void k_maxn(const int* __restrict__ n_idxs) {
    __shared__ int sm[256];
    int m = 0;
    for (int i = threadIdx.x; i < BB; i += 256) m = max(m, __ldg(n_idxs + i));
    sm[threadIdx.x] = m;
    __syncthreads();
    for (int s = 128; s > 0; s >>= 1) {
        if (threadIdx.x < s) sm[threadIdx.x] = max(sm[threadIdx.x], sm[threadIdx.x + s]);
        __syncthreads();
    }
    if (threadIdx.x == 0) g_maxn = (float)sm[0];
}

// ---------------------------------------------------------------------------
// K2: user embedding. grid=B, block=DIM. thread d accumulates over history.
// ---------------------------------------------------------------------------
__global__ void k_user(const int* __restrict__ user_inputs,
                       const int* __restrict__ n_idxs,
                       const float* __restrict__ emb) {
    int b = blockIdx.x, d = threadIdx.x;
    int n = __ldg(n_idxs + b);
    const int* row = user_inputs + b * HIST;
    float acc = 0.f;
    for (int t = 0; t < n; t++) {
        int idx = __ldg(row + t);
        acc += __ldg(emb + (size_t)idx * DIM + d);
    }
    g_user[b * DIM + d] = acc / g_maxn;
}

// ---------------------------------------------------------------------------
// K3 (dominant): level-1 adamic pooling for all 65536 nodes.
// Block = 64 threads handles 4 nodes; 16 threads/node, float4 along DIM.
// grid = NNODE/4
// ---------------------------------------------------------------------------
__global__ void __launch_bounds__(64) k_h1(
    const int*   __restrict__ item_inputs,
    const int*   __restrict__ adj_item,
    const float* __restrict__ adj_adam,
    const float* __restrict__ emb,
    const float* __restrict__ pool_w,   // [128][64]
    const float* __restrict__ pool_b)   // [64]
{
    __shared__ float  s_w[4][SS];
    __shared__ int    s_nbr[4][SS];
    __shared__ int    s_e[4];
    __shared__ float4 s_x4[4][32];      // per node: x = [self(64) || agg(64)]

    int t = threadIdx.x;
    int warp = t >> 5, lane = t & 31;
    int node0 = blockIdx.x << 2;

    // Phase 1: each warp does the 32-way softmax for 2 nodes
    #pragma unroll
    for (int q = 0; q < 2; q++) {
        int ni   = warp * 2 + q;
        int node = node0 + ni;
        int b    = node >> 5, nn = node & 31;
        int item = __ldg(item_inputs + b);
        int e    = __ldg(adj_item + (size_t)item * SS + nn);
        if (lane == 0) s_e[ni] = e;
        float a  = __ldg(adj_adam + (size_t)e * SS + lane);
        int  nbr = __ldg(adj_item + (size_t)e * SS + lane);
        float m = a;
        #pragma unroll
        for (int o = 16; o > 0; o >>= 1) m = fmaxf(m, __shfl_xor_sync(0xffffffffu, m, o));
        float ex = expf(a - m);
        float ssum = ex;
        #pragma unroll
        for (int o = 16; o > 0; o >>= 1) ssum += __shfl_xor_sync(0xffffffffu, ssum, o);
        s_w[ni][lane]   = ex / ssum;
        s_nbr[ni][lane] = nbr;
    }
    __syncthreads();

    // Phase 2: gather + weighted aggregate. thread: ni = t/16, i = t%16 (float4 lane)
    int ni = t >> 4, i = t & 15;
    const float4* emb4 = (const float4*)emb;
    int e = s_e[ni];
    float4 self4 = __ldg(emb4 + (size_t)e * 16 + i);
    float4 agg = make_float4(0.f, 0.f, 0.f, 0.f);
    #pragma unroll 8
    for (int j = 0; j < SS; j++) {
        float  wj = s_w[ni][j];
        float4 v  = __ldg(emb4 + (size_t)s_nbr[ni][j] * 16 + i);
        agg.x += wj * v.x; agg.y += wj * v.y; agg.z += wj * v.z; agg.w += wj * v.w;
    }
    s_x4[ni][i]      = self4;
    s_x4[ni][16 + i] = agg;
    __syncthreads();

    // Phase 3: out[d..d+3] = relu(pool_b + x @ pool_w), d = 4i
    const float4* pw4 = (const float4*)pool_w;   // pw4[k*16 + i] = W[k][4i..4i+3]
    const float4* xr  = (const float4*)&s_x4[ni][0];
    float4 acc = __ldg(((const float4*)pool_b) + i);
    #pragma unroll 8
    for (int k4 = 0; k4 < 32; k4++) {
        float4 xv = xr[k4];
        float4 wA = __ldg(pw4 + (size_t)(k4 * 4 + 0) * 16 + i);
        acc.x += xv.x * wA.x; acc.y += xv.x * wA.y; acc.z += xv.x * wA.z; acc.w += xv.x * wA.w;
        float4 wB = __ldg(pw4 + (size_t)(k4 * 4 + 1) * 16 + i);
        acc.x += xv.y * wB.x; acc.y += xv.y * wB.y; acc.z += xv.y * wB.z; acc.w += xv.y * wB.w;
        float4 wC = __ldg(pw4 + (size_t)(k4 * 4 + 2) * 16 + i);
        acc.x += xv.z * wC.x; acc.y += xv.z * wC.y; acc.z += xv.z * wC.z; acc.w += xv.z * wC.w;
        float4 wD = __ldg(pw4 + (size_t)(k4 * 4 + 3) * 16 + i);
        acc.x += xv.w * wD.x; acc.y += xv.w * wD.y; acc.z += xv.w * wD.z; acc.w += xv.w * wD.w;
    }
    float4 outv = make_float4(fmaxf(acc.x, 0.f), fmaxf(acc.y, 0.f),
                              fmaxf(acc.z, 0.f), fmaxf(acc.w, 0.f));
    ((float4*)g_h1)[(size_t)(node0 + ni) * 16 + i] = outv;
}

// ---------------------------------------------------------------------------
// K4: per-batch level-0 pooling (twice) + final MLP -> score.
// grid = B, block = 64 (thread d = one output dim).
// ---------------------------------------------------------------------------
__global__ void __launch_bounds__(64) k_final(
    const int*   __restrict__ item_inputs,
    const int*   __restrict__ adj_item,
    const float* __restrict__ adj_adam,
    const float* __restrict__ emb,
    const float* __restrict__ pool_w,
    const float* __restrict__ pool_b,
    const float* __restrict__ fc1_w,   // [128][32]
    const float* __restrict__ fc1_b,   // [32]
    const float* __restrict__ fc2_w,   // [32]
    const float* __restrict__ fc2_b)   // [1]
{
    __shared__ float  s_w[SS];
    __shared__ int    s_nbr[SS];
    __shared__ float4 s_x4[32];   // 128 floats
    __shared__ float4 s_in4[32];  // concat(user, item)

    int b = blockIdx.x;
    int d = threadIdx.x;
    int item = __ldg(item_inputs + b);

    // softmax over adj_adam[item] (warp 0)
    if (d < 32) {
        float a  = __ldg(adj_adam + (size_t)item * SS + d);
        int  nbr = __ldg(adj_item + (size_t)item * SS + d);
        float m = a;
        #pragma unroll
        for (int o = 16; o > 0; o >>= 1) m = fmaxf(m, __shfl_xor_sync(0xffffffffu, m, o));
        float ex = expf(a - m);
        float ssum = ex;
        #pragma unroll
        for (int o = 16; o > 0; o >>= 1) ssum += __shfl_xor_sync(0xffffffffu, ssum, o);
        s_w[d]   = ex / ssum;
        s_nbr[d] = nbr;
    }
    __syncthreads();

    float* s_x = (float*)s_x4;

    // pool 1: self = emb[item], neigh = emb[adj_item[item]]
    float self = __ldg(emb + (size_t)item * DIM + d);
    float agg = 0.f;
    #pragma unroll 8
    for (int j = 0; j < SS; j++)
        agg += s_w[j] * __ldg(emb + (size_t)s_nbr[j] * DIM + d);
    s_x[d] = self; s_x[DIM + d] = agg;
    __syncthreads();

    float h0 = __ldg(pool_b + d);
    #pragma unroll 8
    for (int k4 = 0; k4 < 32; k4++) {
        float4 xv = s_x4[k4];
        h0 += xv.x * __ldg(pool_w + (k4 * 4 + 0) * DIM + d);
        h0 += xv.y * __ldg(pool_w + (k4 * 4 + 1) * DIM + d);
        h0 += xv.z * __ldg(pool_w + (k4 * 4 + 2) * DIM + d);
        h0 += xv.w * __ldg(pool_w + (k4 * 4 + 3) * DIM + d);
    }
    h0 = fmaxf(h0, 0.f);

    // pool 2: self = h0, neigh = g_h1[b], weights = same s_w
    const float* h1b = g_h1 + (size_t)b * SS * DIM;
    float agg2 = 0.f;
    #pragma unroll 8
    for (int j = 0; j < SS; j++)
        agg2 += s_w[j] * h1b[j * DIM + d];
    __syncthreads();                 // MLP1 reads of s_x done before rewrite
    s_x[d] = h0; s_x[DIM + d] = agg2;
    __syncthreads();

    float v = __ldg(pool_b + d);
    #pragma unroll 8
    for (int k4 = 0; k4 < 32; k4++) {
        float4 xv = s_x4[k4];
        v += xv.x * __ldg(pool_w + (k4 * 4 + 0) * DIM + d);
        v += xv.y * __ldg(pool_w + (k4 * 4 + 1) * DIM + d);
        v += xv.z * __ldg(pool_w + (k4 * 4 + 2) * DIM + d);
        v += xv.w * __ldg(pool_w + (k4 * 4 + 3) * DIM + d);
    }
    v = fmaxf(v, 0.f);               // item_emb[d]

    // final MLP: concat(user_emb, item_emb) -> 32 -> 1
    float* s_in = (float*)s_in4;
    s_in[d]       = g_user[b * DIM + d];
    s_in[DIM + d] = v;
    __syncthreads();

    if (d < 32) {
        float y = __ldg(fc1_b + d);
        #pragma unroll 8
        for (int k4 = 0; k4 < 32; k4++) {
            float4 xv = s_in4[k4];
            y += xv.x * __ldg(fc1_w + (k4 * 4 + 0) * 32 + d);
            y += xv.y * __ldg(fc1_w + (k4 * 4 + 1) * 32 + d);
            y += xv.z * __ldg(fc1_w + (k4 * 4 + 2) * 32 + d);
            y += xv.w * __ldg(fc1_w + (k4 * 4 + 3) * 32 + d);
        }
        y = fmaxf(y, 0.f);
        float p = y * __ldg(fc2_w + d);
        #pragma unroll
        for (int o = 16; o > 0; o >>= 1) p += __shfl_xor_sync(0xffffffffu, p, o);
        if (d == 0) g_scores[b] = p + __ldg(fc2_b);
    }
}

// ---------------------------------------------------------------------------
// K5: softmax over the B=2048 scores -> d_out. One block, 1024 threads.
// ---------------------------------------------------------------------------
__global__ void k_softmax(float* __restrict__ out) {
    __shared__ float red[1024];
    int t = threadIdx.x;
    float a0 = g_scores[t];
    float a1 = g_scores[t + 1024];

    red[t] = fmaxf(a0, a1);
    __syncthreads();
    for (int s = 512; s > 0; s >>= 1) {
        if (t < s) red[t] = fmaxf(red[t], red[t + s]);
        __syncthreads();
    }
    float gm = red[0];
    __syncthreads();

    float e0 = expf(a0 - gm), e1 = expf(a1 - gm);
    red[t] = e0 + e1;
    __syncthreads();
    for (int s = 512; s > 0; s >>= 1) {
        if (t < s) red[t] += red[t + s];
        __syncthreads();
    }
    float inv = 1.f / red[0];
    out[t]        = e0 * inv;
    out[t + 1024] = e1 * inv;
}

// ---------------------------------------------------------------------------
// Launch
// ---------------------------------------------------------------------------
extern "C" void kernel_launch(void* const* d_in, const int* in_sizes, int n_in,
                              void* d_out, int out_size) {
    const int*   user_inputs = (const int*)  d_in[0];
    const int*   item_inputs = (const int*)  d_in[1];
    const int*   n_idxs      = (const int*)  d_in[2];
    const float* emb         = (const float*)d_in[3];
    const int*   adj_item    = (const int*)  d_in[4];
    const float* adj_adam    = (const float*)d_in[5];
    const float* pool_w      = (const float*)d_in[6];
    const float* pool_b      = (const float*)d_in[7];
    const float* fc1_w       = (const float*)d_in[8];
    const float* fc1_b       = (const float*)d_in[9];
    const float* fc2_w       = (const float*)d_in[10];
    const float* fc2_b       = (const float*)d_in[11];
    float* out = (float*)d_out;

    k_maxn<<<1, 256>>>(n_idxs);
    k_user<<<BB, DIM>>>(user_inputs, n_idxs, emb);
    k_h1<<<NNODE / 4, 64>>>(item_inputs, adj_item, adj_adam, emb, pool_w, pool_b);
    k_final<<<BB, 64>>>(item_inputs, adj_item, adj_adam, emb,
                        pool_w, pool_b, fc1_w, fc1_b, fc2_w, fc2_b);
    k_softmax<<<1, 1024>>>(out);
}